// round 12
// baseline (speedup 1.0000x reference)
#include <cuda_runtime.h>
#include <cuda_bf16.h>
#include <cstdint>

// ---------------- problem constants ----------------
#define Bsz 4
#define Nq  100
#define Mt  50
#define HWP 65536
#define KS  32                  // k per stage
#define NKT (HWP / KS)          // 2048 k-tiles per batch
#define CTAS_PER_B 74           // 296 CTAs = 2 per SM, one wave
#define NCTA (CTAS_PER_B * Bsz)
#define THREADS 256             // 8 warps per CTA

// per-stage slot: A[128 rows x 128B] (x bytes 0-63, sig 64-127) 16K | B[64 x 128B] 8K
#define SLOT_SZ 24576
#define SMEM_BYTES (2 * SLOT_SZ + 1024)

// ---------------- fused scratch (one memset) ----------------
#define OFF_G1   0
#define OFF_G2   (Bsz * Nq * Mt)
#define OFF_SNPM (2 * Bsz * Nq * Mt)
#define OFF_SNSP (2 * Bsz * Nq * Mt + Bsz * Nq)
#define OFF_SMT  (2 * Bsz * Nq * Mt + 2 * Bsz * Nq)
#define OFF_CTR  (2 * Bsz * Nq * Mt + 2 * Bsz * Nq + Bsz * Mt)
#define SCRATCH_N (OFF_CTR + 1)
__device__ float g_s[SCRATCH_N];

__device__ __forceinline__ uint32_t smem_u32(const void* p) {
    uint32_t a;
    asm("{ .reg .u64 t; cvta.to.shared.u64 t, %1; cvt.u32.u64 %0, t; }" : "=r"(a) : "l"(p));
    return a;
}
__device__ __forceinline__ uint32_t SW(uint32_t o) { return o ^ ((o >> 3) & 0x70); }

#define LDSM4(r0, r1, r2, r3, addr) \
    asm volatile("ldmatrix.sync.aligned.m8n8.x4.shared.b16 {%0,%1,%2,%3}, [%4];" \
                 : "=r"(r0), "=r"(r1), "=r"(r2), "=r"(r3) : "r"(addr))

#define MMA16816(c, a, b0, b1) \
    asm volatile("mma.sync.aligned.m16n8k16.row.col.f32.bf16.bf16.f32 " \
                 "{%0,%1,%2,%3},{%4,%5,%6,%7},{%8,%9},{%0,%1,%2,%3};" \
                 : "+f"((c)[0]), "+f"((c)[1]), "+f"((c)[2]), "+f"((c)[3]) \
                 : "r"((a)[0]), "r"((a)[1]), "r"((a)[2]), "r"((a)[3]), "r"(b0), "r"(b1))

__global__ void __launch_bounds__(THREADS, 2)
cost_main(const float* __restrict__ X, const float* __restrict__ T,
          const float* __restrict__ logits, const float* __restrict__ style,
          const int* __restrict__ sids, float* __restrict__ out)
{
    extern __shared__ char dsm[];
    const uint32_t sb = (smem_u32(dsm) + 1023u) & ~1023u;
    __shared__ int slast;

    const int tid = threadIdx.x;
    const int b   = blockIdx.y;
    const int r   = blockIdx.x;
    const int t0  = (r * NKT) / CTAS_PER_B;
    const int nst = ((r + 1) * NKT) / CTAS_PER_B - t0;

    // zero both slots (rows >=101 of A / >=51 of B stay zero forever)
    for (int i = tid; i < (2 * SLOT_SZ) / 8; i += THREADS)
        asm volatile("st.shared.b64 [%0], %1;" :: "r"(sb + i * 8), "l"(0ull) : "memory");
    __syncthreads();
    // ones: A row 100 (x half -> sum_k t; sig half written but discarded) ; B row 50 -> sum_k sigma
    const uint64_t ones8 = 0x3F803F803F803F80ull;
    if (tid < 16) {          // A row 100: full 128B row, both slots
        uint32_t o = SW(100u * 128u + (uint32_t)tid * 8u);
        asm volatile("st.shared.b64 [%0], %1;" :: "r"(sb + o), "l"(ones8) : "memory");
        asm volatile("st.shared.b64 [%0], %1;" :: "r"(sb + SLOT_SZ + o), "l"(ones8) : "memory");
    } else if (tid < 24) {   // B row 50: bytes 0-63 (k 0..31), both slots
        uint32_t o = SW(50u * 128u + (uint32_t)(tid - 16) * 8u) + 16384u;
        asm volatile("st.shared.b64 [%0], %1;" :: "r"(sb + o), "l"(ones8) : "memory");
        asm volatile("st.shared.b64 [%0], %1;" :: "r"(sb + SLOT_SZ + o), "l"(ones8) : "memory");
    }
    __syncthreads();

    const float* Xb = X + (size_t)b * Nq * HWP;
    const float* Tb = T + (size_t)b * Mt * HWP;

    float4 la[4], lb[2];
    auto LOADS = [&](int s) {
        if (s >= nst) return;
        const int kb = (t0 + s) * KS;
        #pragma unroll
        for (int j = 0; j < 4; j++) {
            int idx = tid + THREADS * j;
            if (idx < 800) {                      // 100 rows x 8 float4
                int row = idx >> 3, c4 = idx & 7;
                la[j] = *(const float4*)(Xb + (size_t)row * HWP + kb + c4 * 4);
            }
        }
        #pragma unroll
        for (int j = 0; j < 2; j++) {
            int idx = tid + THREADS * j;
            if (idx < 400) {                      // 50 rows x 8 float4
                int row = idx >> 3, c4 = idx & 7;
                lb[j] = *(const float4*)(Tb + (size_t)row * HWP + kb + c4 * 4);
            }
        }
    };
    LOADS(0);

    // MMA geometry: warps 0..6 each own rows 16w..16w+15, all 56 cols, BOTH GEMMs
    const int w = tid >> 5, l = tid & 31;
    const bool mma_w = (w < 7);
    const int Rr = w * 16;
    const uint32_t rowA = (uint32_t)(Rr + (l & 15)) * 128u + (uint32_t)(l >> 4) * 16u;
    const uint32_t rowB = (uint32_t)(l & 15) * 128u + (uint32_t)(l >> 4) * 16u;

    float cx[7][4], cs[7][4];
    #pragma unroll
    for (int nb = 0; nb < 7; nb++)
        #pragma unroll
        for (int e = 0; e < 4; e++) { cx[nb][e] = 0.f; cs[nb][e] = 0.f; }

    float spm[4] = {0.f, 0.f, 0.f, 0.f};   // sum relu(x)
    float spl[4] = {0.f, 0.f, 0.f, 0.f};   // sum log2(1+e^-|x|)

    for (int s = 0; s < nst; s++) {
        const uint32_t BUF = sb + (uint32_t)(s & 1) * SLOT_SZ;
        const uint32_t BT  = BUF + 16384u;

        // ---- convert: fp32 -> (bf16 x | bf16 sigmoid packed per 128B row) ----
        #pragma unroll
        for (int j = 0; j < 4; j++) {
            int idx = tid + THREADS * j;
            if (idx < 800) {
                int row = idx >> 3, c4 = idx & 7;
                float v[4] = {la[j].x, la[j].y, la[j].z, la[j].w};
                float sg[4];
                #pragma unroll
                for (int e = 0; e < 4; e++) {
                    float x = v[e], ea, lg;
                    asm("ex2.approx.f32 %0, %1;" : "=f"(ea) : "f"(-1.4426950408889634f * fabsf(x)));
                    float d = 1.f + ea;
                    asm("lg2.approx.f32 %0, %1;" : "=f"(lg) : "f"(d));
                    spm[j] += fmaxf(x, 0.f);
                    spl[j] += lg;
                    float y = fmaf(-0.4566f, ea, 0.9566f);       // ~1/d seed, d in (1,2]
                    y = fmaf(y, fmaf(-d, y, 1.f), y);            // Newton 1
                    sg[e] = (x >= 0.f) ? y : (1.f - y);
                }
                uint32_t xw0, xw1, sw0, sw1;
                asm("cvt.rn.bf16x2.f32 %0, %1, %2;" : "=r"(xw0) : "f"(v[1]),  "f"(v[0]));
                asm("cvt.rn.bf16x2.f32 %0, %1, %2;" : "=r"(xw1) : "f"(v[3]),  "f"(v[2]));
                asm("cvt.rn.bf16x2.f32 %0, %1, %2;" : "=r"(sw0) : "f"(sg[1]), "f"(sg[0]));
                asm("cvt.rn.bf16x2.f32 %0, %1, %2;" : "=r"(sw1) : "f"(sg[3]), "f"(sg[2]));
                uint32_t base = (uint32_t)row * 128u + (uint32_t)c4 * 8u;
                asm volatile("st.shared.v2.b32 [%0], {%1, %2};"
                             :: "r"(BUF + SW(base)), "r"(xw0), "r"(xw1) : "memory");
                asm volatile("st.shared.v2.b32 [%0], {%1, %2};"
                             :: "r"(BUF + SW(base + 64u)), "r"(sw0), "r"(sw1) : "memory");
            }
        }
        #pragma unroll
        for (int j = 0; j < 2; j++) {
            int idx = tid + THREADS * j;
            if (idx < 400) {
                int row = idx >> 3, c4 = idx & 7;
                uint32_t w0, w1;
                asm("cvt.rn.bf16x2.f32 %0, %1, %2;" : "=r"(w0) : "f"(lb[j].y), "f"(lb[j].x));
                asm("cvt.rn.bf16x2.f32 %0, %1, %2;" : "=r"(w1) : "f"(lb[j].w), "f"(lb[j].z));
                uint32_t a = BT + SW((uint32_t)row * 128u + (uint32_t)c4 * 8u);
                asm volatile("st.shared.v2.b32 [%0], {%1, %2};" :: "r"(a), "r"(w0), "r"(w1) : "memory");
            }
        }
        __syncthreads();

        LOADS(s + 1);   // gmem latency hides under MMA phase (and the peer CTA's conv)

        // ---- mma: 2 k16-iters, 4 B-groups of 16 cols, both GEMMs per warp ----
        if (mma_w) {
            #pragma unroll
            for (int i = 0; i < 2; i++) {
                uint32_t ko = 32u * i;
                uint32_t ax[4], as[4];
                LDSM4(ax[0], ax[1], ax[2], ax[3], BUF + SW(rowA + ko));
                LDSM4(as[0], as[1], as[2], as[3], BUF + SW(rowA + 64u + ko));
                #pragma unroll
                for (int gq = 0; gq < 4; gq++) {
                    uint32_t q[4];
                    LDSM4(q[0], q[1], q[2], q[3], BT + SW(rowB + (uint32_t)gq * 2048u + ko));
                    MMA16816(cx[2 * gq], ax, q[0], q[2]);
                    MMA16816(cs[2 * gq], as, q[0], q[2]);
                    if (gq < 3) {
                        MMA16816(cx[2 * gq + 1], ax, q[1], q[3]);
                        MMA16816(cs[2 * gq + 1], as, q[1], q[3]);
                    }
                }
            }
        }
    }

    // ---- combine: softplus row sums ----
    #pragma unroll
    for (int j = 0; j < 4; j++) {
        int idx = tid + THREADS * j;
        if (idx < 800)
            atomicAdd(&g_s[OFF_SNSP + b * Nq + (idx >> 3)],
                      spm[j] + 0.6931471805599453f * spl[j]);
    }

    // ---- combine: accumulator fragments ----
    auto emit = [&](int rr, int m, float vx, float vs) {
        if (rr < Nq) {
            if (m < Mt) {
                atomicAdd(&g_s[OFF_G1 + (b * Nq + rr) * Mt + m], vx);
                atomicAdd(&g_s[OFF_G2 + (b * Nq + rr) * Mt + m], vs);
            } else if (m == Mt) {
                atomicAdd(&g_s[OFF_SNPM + b * Nq + rr], vs);
            }
        } else if (rr == Nq && m < Mt) {
            atomicAdd(&g_s[OFF_SMT + b * Mt + m], vx);
        }
    };
    if (mma_w) {
        #pragma unroll
        for (int nb = 0; nb < 7; nb++) {
            const int m0 = nb * 8 + (l & 3) * 2;
            const int r0 = Rr + (l >> 2);
            emit(r0,     m0,     cx[nb][0], cs[nb][0]);
            emit(r0,     m0 + 1, cx[nb][1], cs[nb][1]);
            emit(r0 + 8, m0,     cx[nb][2], cs[nb][2]);
            emit(r0 + 8, m0 + 1, cx[nb][3], cs[nb][3]);
        }
    }

    // ---- grid-wide completion: last CTA runs the epilogue ----
    __threadfence();
    __syncthreads();
    if (tid == 0) {
        int v = atomicAdd((int*)(g_s + OFF_CTR), 1);
        slast = (v == NCTA - 1);
    }
    __syncthreads();
    if (slast) {
        __threadfence();
        for (int i = tid; i < Bsz * Nq * Mt; i += THREADS) {
            const int m  = i % Mt;
            const int n  = (i / Mt) % Nq;
            const int bb = i / (Nq * Mt);

            const float l0 = logits[(bb * Nq + n) * 2 + 0];
            const float l1 = logits[(bb * Nq + n) * 2 + 1];
            const float p1 = __fdividef(1.f, 1.f + __expf(l0 - l1));

            const float* st = style + (bb * Nq + n) * 4;
            const float s0 = st[0], s1 = st[1], s2 = st[2], s3 = st[3];
            const float mx = fmaxf(fmaxf(s0, s1), fmaxf(s2, s3));
            const float e0 = __expf(s0 - mx), e1 = __expf(s1 - mx);
            const float e2 = __expf(s2 - mx), e3 = __expf(s3 - mx);
            const float inv = __fdividef(1.f, e0 + e1 + e2 + e3);

            const float snsp = g_s[OFF_SNSP + bb * Nq + n];
            const float snpm = g_s[OFF_SNPM + bb * Nq + n];
            const float G1v  = g_s[OFF_G1 + (bb * Nq + n) * Mt + m];
            const float G2v  = g_s[OFF_G2 + (bb * Nq + n) * Mt + m];
            const float smt  = g_s[OFF_SMT + bb * Mt + m];

            const float cmask = (snsp - G1v) * (1.0f / (float)HWP);
            const float cdice = 1.f - __fdividef(2.f * G2v + 1.f, snpm + smt + 1.f);

            int sid = sids[bb * Mt + m];
            sid = sid < 0 ? 0 : (sid > 3 ? 3 : sid);
            float pr = (sid == 0) ? e0 : (sid == 1) ? e1 : (sid == 2) ? e2 : e3;
            pr *= inv;

            float c = -2.f * p1 + 5.f * cmask + 5.f * cdice - pr;
            if (!isfinite(c)) c = isnan(c) ? 10000.f : (c > 0.f ? 10000.f : -10000.f);
            out[(bb * Nq + n) * Mt + m] = c;
        }
    }
}

extern "C" void kernel_launch(void* const* d_in, const int* in_sizes, int n_in,
                              void* d_out, int out_size)
{
    const float* pred_logits = (const float*)d_in[0];  // [4,100,2]
    const float* pred_masks  = (const float*)d_in[1];  // [4,100,256,256]
    const float* pred_style  = (const float*)d_in[2];  // [4,100,4]
    const float* tgt_masks   = (const float*)d_in[3];  // [4,50,256,256]
    const int*   styles      = (const int*)d_in[4];    // [4,50]
    float* out = (float*)d_out;                        // [4,100,50]

    cudaFuncSetAttribute(cost_main, cudaFuncAttributeMaxDynamicSharedMemorySize, SMEM_BYTES);

    void* scratch = nullptr;
    cudaGetSymbolAddress(&scratch, g_s);
    cudaMemsetAsync(scratch, 0, SCRATCH_N * sizeof(float), 0);

    dim3 gmain(CTAS_PER_B, Bsz);
    cost_main<<<gmain, THREADS, SMEM_BYTES>>>(pred_masks, tgt_masks,
                                              pred_logits, pred_style, styles, out);
}

// round 13
// speedup vs baseline: 1.1132x; 1.1132x over previous
#include <cuda_runtime.h>
#include <cuda_bf16.h>
#include <cstdint>

// ---------------- problem constants ----------------
#define Bsz 4
#define Nq  100
#define Mt  50
#define HWP 65536
#define KS  64                  // k per stage
#define NKT (HWP / KS)          // 1024 k-tiles per batch
#define CTAS_PER_B 37           // 148 CTAs = one full wave
#define NCTA (CTAS_PER_B * Bsz)
#define THREADS 512             // 16 warps

// per-stage smem buffer: A_x[128x64]bf16 (16K) | A_s (16K) | B_t[64x64]bf16 (8K)
#define BUF_SZ 40960
#define SMEM_BYTES (2 * BUF_SZ + 1024)

// ---------------- fused scratch (one memset) ----------------
#define OFF_G1   0
#define OFF_G2   (Bsz * Nq * Mt)
#define OFF_SNPM (2 * Bsz * Nq * Mt)
#define OFF_SNSP (2 * Bsz * Nq * Mt + Bsz * Nq)
#define OFF_SMT  (2 * Bsz * Nq * Mt + 2 * Bsz * Nq)
#define OFF_CTR  (2 * Bsz * Nq * Mt + 2 * Bsz * Nq + Bsz * Mt)
#define SCRATCH_N (OFF_CTR + 1)
__device__ float g_s[SCRATCH_N];

__device__ __forceinline__ uint32_t smem_u32(const void* p) {
    uint32_t a;
    asm("{ .reg .u64 t; cvta.to.shared.u64 t, %1; cvt.u32.u64 %0, t; }" : "=r"(a) : "l"(p));
    return a;
}
__device__ __forceinline__ uint32_t SW(uint32_t o) { return o ^ ((o >> 3) & 0x70); }

#define LDSM4(r0, r1, r2, r3, addr) \
    asm volatile("ldmatrix.sync.aligned.m8n8.x4.shared.b16 {%0,%1,%2,%3}, [%4];" \
                 : "=r"(r0), "=r"(r1), "=r"(r2), "=r"(r3) : "r"(addr))

#define MMA16816(c, a, b0, b1) \
    asm volatile("mma.sync.aligned.m16n8k16.row.col.f32.bf16.bf16.f32 " \
                 "{%0,%1,%2,%3},{%4,%5,%6,%7},{%8,%9},{%0,%1,%2,%3};" \
                 : "+f"((c)[0]), "+f"((c)[1]), "+f"((c)[2]), "+f"((c)[3]) \
                 : "r"((a)[0]), "r"((a)[1]), "r"((a)[2]), "r"((a)[3]), "r"(b0), "r"(b1))

__global__ void __launch_bounds__(THREADS, 1)
cost_main(const float* __restrict__ X, const float* __restrict__ T,
          const float* __restrict__ logits, const float* __restrict__ style,
          const int* __restrict__ sids, float* __restrict__ out)
{
    extern __shared__ char dsm[];
    const uint32_t sb = (smem_u32(dsm) + 1023u) & ~1023u;
    __shared__ int slast;

    const int tid = threadIdx.x;
    const int b   = blockIdx.y;
    const int r   = blockIdx.x;
    const int t0  = (r * NKT) / CTAS_PER_B;
    const int nst = ((r + 1) * NKT) / CTAS_PER_B - t0;

    // zero both stage buffers once (zero rows/cols stay zero forever)
    for (int i = tid; i < (2 * BUF_SZ) / 8; i += THREADS)
        asm volatile("st.shared.b64 [%0], %1;" :: "r"(sb + i * 8), "l"(0ull) : "memory");
    __syncthreads();
    // ones rows: A_x row 100 (-> sum_k t), B row 50 (-> sum_k sigma)
    const uint64_t ones8 = 0x3F803F803F803F80ull;
    if (tid < 16) {
        uint32_t o = SW(100u * 128u + (uint32_t)tid * 8u);
        asm volatile("st.shared.b64 [%0], %1;" :: "r"(sb + o), "l"(ones8) : "memory");
        asm volatile("st.shared.b64 [%0], %1;" :: "r"(sb + BUF_SZ + o), "l"(ones8) : "memory");
    } else if (tid < 32) {
        uint32_t o = SW(50u * 128u + (uint32_t)(tid - 16) * 8u) + 32768u;
        asm volatile("st.shared.b64 [%0], %1;" :: "r"(sb + o), "l"(ones8) : "memory");
        asm volatile("st.shared.b64 [%0], %1;" :: "r"(sb + BUF_SZ + o), "l"(ones8) : "memory");
    }
    __syncthreads();

    const float* Xb = X + (size_t)b * Nq * HWP;
    const float* Tb = T + (size_t)b * Mt * HWP;

    float4 la[4], lb[2];
    auto LOADS = [&](int s) {
        if (s >= nst) return;
        const int kb = (t0 + s) * KS;
        #pragma unroll
        for (int j = 0; j < 4; j++) {
            int idx = tid + THREADS * j;
            if (idx < 1600) {
                int row = idx >> 4, c4 = idx & 15;
                la[j] = *(const float4*)(Xb + (size_t)row * HWP + kb + c4 * 4);
            }
        }
        #pragma unroll
        for (int j = 0; j < 2; j++) {
            int idx = tid + THREADS * j;
            if (idx < 800) {
                int row = idx >> 4, c4 = idx & 15;
                lb[j] = *(const float4*)(Tb + (size_t)row * HWP + kb + c4 * 4);
            }
        }
    };
    LOADS(0);

    // per-warp MMA geometry: 14 active warps, M=112 (7 m16 tiles) x N=56/64
    const int w = tid >> 5, l = tid & 31;
    const bool mma_w = (w < 14);
    const int Rr = (w >> 1) * 16, Cc = (w & 1) * 32;
    const bool full_n = ((w & 1) == 0);    // right half skips cols 56..63 (all-zero)
    const uint32_t rowA  = (uint32_t)(Rr + (l & 15)) * 128u + (uint32_t)(l >> 4) * 16u;
    const uint32_t rowB0 = (uint32_t)(Cc + (l & 15)) * 128u + (uint32_t)(l >> 4) * 16u;
    const uint32_t rowB1 = rowB0 + 16u * 128u;

    float cx[4][4], cs[4][4];
    #pragma unroll
    for (int nb = 0; nb < 4; nb++)
        #pragma unroll
        for (int e = 0; e < 4; e++) { cx[nb][e] = 0.f; cs[nb][e] = 0.f; }

    float ssp[4] = {0.f, 0.f, 0.f, 0.f};   // sum softplus(x)

    for (int s = 0; s < nst; s++) {
        const uint32_t BUF = sb + (uint32_t)(s & 1) * BUF_SZ;
        const uint32_t BTb = BUF + 32768u;

        // ---- convert: fp32 -> (bf16 x, bf16 sigmoid) + softplus partials ----
        #pragma unroll
        for (int j = 0; j < 4; j++) {
            int idx = tid + THREADS * j;
            if (idx < 1600) {
                int row = idx >> 4, c4 = idx & 15;
                float v[4] = {la[j].x, la[j].y, la[j].z, la[j].w};
                float sg[4];
                #pragma unroll
                for (int e = 0; e < 4; e++) {
                    float x = v[e], ea, lg, y;
                    asm("ex2.approx.f32 %0, %1;" : "=f"(ea) : "f"(-1.4426950408889634f * fabsf(x)));
                    float d = 1.f + ea;
                    asm("lg2.approx.f32 %0, %1;" : "=f"(lg) : "f"(d));
                    ssp[j] += fmaf(0.6931471805599453f, lg, fmaxf(x, 0.f));
                    asm("rcp.approx.f32 %0, %1;" : "=f"(y) : "f"(d));
                    sg[e] = (x >= 0.f) ? y : (1.f - y);
                }
                uint32_t xw0, xw1, sw0, sw1;
                asm("cvt.rn.bf16x2.f32 %0, %1, %2;" : "=r"(xw0) : "f"(v[1]),  "f"(v[0]));
                asm("cvt.rn.bf16x2.f32 %0, %1, %2;" : "=r"(xw1) : "f"(v[3]),  "f"(v[2]));
                asm("cvt.rn.bf16x2.f32 %0, %1, %2;" : "=r"(sw0) : "f"(sg[1]), "f"(sg[0]));
                asm("cvt.rn.bf16x2.f32 %0, %1, %2;" : "=r"(sw1) : "f"(sg[3]), "f"(sg[2]));
                uint32_t a = BUF + SW((uint32_t)row * 128u + (uint32_t)c4 * 8u);
                asm volatile("st.shared.v2.b32 [%0], {%1, %2};" :: "r"(a), "r"(xw0), "r"(xw1) : "memory");
                asm volatile("st.shared.v2.b32 [%0], {%1, %2};" :: "r"(a + 16384u), "r"(sw0), "r"(sw1) : "memory");
            }
        }
        #pragma unroll
        for (int j = 0; j < 2; j++) {
            int idx = tid + THREADS * j;
            if (idx < 800) {
                int row = idx >> 4, c4 = idx & 15;
                uint32_t w0, w1;
                asm("cvt.rn.bf16x2.f32 %0, %1, %2;" : "=r"(w0) : "f"(lb[j].y), "f"(lb[j].x));
                asm("cvt.rn.bf16x2.f32 %0, %1, %2;" : "=r"(w1) : "f"(lb[j].w), "f"(lb[j].z));
                uint32_t a = BTb + SW((uint32_t)row * 128u + (uint32_t)c4 * 8u);
                asm volatile("st.shared.v2.b32 [%0], {%1, %2};" :: "r"(a), "r"(w0), "r"(w1) : "memory");
            }
        }
        __syncthreads();

        LOADS(s + 1);   // gmem latency hides under MMA phase

        // ---- mma phase on buffer (s&1) ----
        if (mma_w) {
            #pragma unroll
            for (int i = 0; i < 4; i++) {
                uint32_t aax = BUF + SW(rowA + 32u * i);
                uint32_t ax[4], as[4], q[4], p[4];
                LDSM4(ax[0], ax[1], ax[2], ax[3], aax);
                LDSM4(as[0], as[1], as[2], as[3], aax + 16384u);
                LDSM4(q[0], q[1], q[2], q[3], BTb + SW(rowB0 + 32u * i));
                LDSM4(p[0], p[1], p[2], p[3], BTb + SW(rowB1 + 32u * i));
                MMA16816(cx[0], ax, q[0], q[2]);
                MMA16816(cx[1], ax, q[1], q[3]);
                MMA16816(cx[2], ax, p[0], p[2]);
                MMA16816(cs[0], as, q[0], q[2]);
                MMA16816(cs[1], as, q[1], q[3]);
                MMA16816(cs[2], as, p[0], p[2]);
                if (full_n) {
                    MMA16816(cx[3], ax, p[1], p[3]);
                    MMA16816(cs[3], as, p[1], p[3]);
                }
            }
        }
    }

    // ---- combine: softplus row sums ----
    #pragma unroll
    for (int j = 0; j < 4; j++) {
        int idx = tid + THREADS * j;
        if (idx < 1600)
            atomicAdd(&g_s[OFF_SNSP + b * Nq + (idx >> 4)], ssp[j]);
    }

    // ---- combine: accumulator fragments ----
    auto emit = [&](int rr, int m, float vx, float vs) {
        if (rr < Nq) {
            if (m < Mt) {
                atomicAdd(&g_s[OFF_G1 + (b * Nq + rr) * Mt + m], vx);
                atomicAdd(&g_s[OFF_G2 + (b * Nq + rr) * Mt + m], vs);
            } else if (m == Mt) {
                atomicAdd(&g_s[OFF_SNPM + b * Nq + rr], vs);
            }
        } else if (rr == Nq && m < Mt) {
            atomicAdd(&g_s[OFF_SMT + b * Mt + m], vx);
        }
    };
    if (mma_w) {
        #pragma unroll
        for (int nb = 0; nb < 4; nb++) {
            if (nb == 3 && !full_n) continue;
            const int m0 = Cc + nb * 8 + (l & 3) * 2;
            const int r0 = Rr + (l >> 2);
            emit(r0,     m0,     cx[nb][0], cs[nb][0]);
            emit(r0,     m0 + 1, cx[nb][1], cs[nb][1]);
            emit(r0 + 8, m0,     cx[nb][2], cs[nb][2]);
            emit(r0 + 8, m0 + 1, cx[nb][3], cs[nb][3]);
        }
    }

    // ---- grid-wide completion: last CTA runs the epilogue ----
    __threadfence();
    __syncthreads();
    if (tid == 0) {
        int v = atomicAdd((int*)(g_s + OFF_CTR), 1);
        slast = (v == NCTA - 1);
    }
    __syncthreads();
    if (slast) {
        __threadfence();
        for (int i = tid; i < Bsz * Nq * Mt; i += THREADS) {
            const int m  = i % Mt;
            const int n  = (i / Mt) % Nq;
            const int bb = i / (Nq * Mt);

            const float l0 = logits[(bb * Nq + n) * 2 + 0];
            const float l1 = logits[(bb * Nq + n) * 2 + 1];
            const float p1 = __fdividef(1.f, 1.f + __expf(l0 - l1));

            const float* st = style + (bb * Nq + n) * 4;
            const float s0 = st[0], s1 = st[1], s2 = st[2], s3 = st[3];
            const float mx = fmaxf(fmaxf(s0, s1), fmaxf(s2, s3));
            const float e0 = __expf(s0 - mx), e1 = __expf(s1 - mx);
            const float e2 = __expf(s2 - mx), e3 = __expf(s3 - mx);
            const float inv = __fdividef(1.f, e0 + e1 + e2 + e3);

            const float snsp = g_s[OFF_SNSP + bb * Nq + n];
            const float snpm = g_s[OFF_SNPM + bb * Nq + n];
            const float G1v  = g_s[OFF_G1 + (bb * Nq + n) * Mt + m];
            const float G2v  = g_s[OFF_G2 + (bb * Nq + n) * Mt + m];
            const float smt  = g_s[OFF_SMT + bb * Mt + m];

            const float cmask = (snsp - G1v) * (1.0f / (float)HWP);
            const float cdice = 1.f - __fdividef(2.f * G2v + 1.f, snpm + smt + 1.f);

            int sid = sids[bb * Mt + m];
            sid = sid < 0 ? 0 : (sid > 3 ? 3 : sid);
            float pr = (sid == 0) ? e0 : (sid == 1) ? e1 : (sid == 2) ? e2 : e3;
            pr *= inv;

            float c = -2.f * p1 + 5.f * cmask + 5.f * cdice - pr;
            if (!isfinite(c)) c = isnan(c) ? 10000.f : (c > 0.f ? 10000.f : -10000.f);
            out[(bb * Nq + n) * Mt + m] = c;
        }
    }
}

extern "C" void kernel_launch(void* const* d_in, const int* in_sizes, int n_in,
                              void* d_out, int out_size)
{
    const float* pred_logits = (const float*)d_in[0];  // [4,100,2]
    const float* pred_masks  = (const float*)d_in[1];  // [4,100,256,256]
    const float* pred_style  = (const float*)d_in[2];  // [4,100,4]
    const float* tgt_masks   = (const float*)d_in[3];  // [4,50,256,256]
    const int*   styles      = (const int*)d_in[4];    // [4,50]
    float* out = (float*)d_out;                        // [4,100,50]

    cudaFuncSetAttribute(cost_main, cudaFuncAttributeMaxDynamicSharedMemorySize, SMEM_BYTES);

    void* scratch = nullptr;
    cudaGetSymbolAddress(&scratch, g_s);
    cudaMemsetAsync(scratch, 0, SCRATCH_N * sizeof(float), 0);

    dim3 gmain(CTAS_PER_B, Bsz);
    cost_main<<<gmain, THREADS, SMEM_BYTES>>>(pred_masks, tgt_masks,
                                              pred_logits, pred_style, styles, out);
}

// round 14
// speedup vs baseline: 1.4526x; 1.3049x over previous
#include <cuda_runtime.h>
#include <cuda_bf16.h>
#include <cstdint>

// ---------------- problem constants ----------------
#define Bsz 4
#define Nq  100
#define Mt  50
#define HWP 65536
#define KS  64                  // k per stage
#define NKT (HWP / KS)          // 1024 k-tiles per batch
#define CTAS_PER_B 37           // 148 CTAs = one full wave
#define THREADS 512             // 16 warps

// per-stage smem buffer: A_x[128x64]bf16 (16K) | A_s (16K) | B_t[64x64]bf16 (8K)
#define BUF_SZ 40960
#define SMEM_BYTES (2 * BUF_SZ + 1024)

// ---------------- fused scratch (one memset) ----------------
#define OFF_G1   0
#define OFF_G2   (Bsz * Nq * Mt)
#define OFF_SNPM (2 * Bsz * Nq * Mt)
#define OFF_SNSP (2 * Bsz * Nq * Mt + Bsz * Nq)
#define OFF_SMT  (2 * Bsz * Nq * Mt + 2 * Bsz * Nq)
#define SCRATCH_N (2 * Bsz * Nq * Mt + 2 * Bsz * Nq + Bsz * Mt)
__device__ float g_s[SCRATCH_N];

__device__ __forceinline__ uint32_t smem_u32(const void* p) {
    uint32_t a;
    asm("{ .reg .u64 t; cvta.to.shared.u64 t, %1; cvt.u32.u64 %0, t; }" : "=r"(a) : "l"(p));
    return a;
}
__device__ __forceinline__ uint32_t SW(uint32_t o) { return o ^ ((o >> 3) & 0x70); }

#define LDSM4(r0, r1, r2, r3, addr) \
    asm volatile("ldmatrix.sync.aligned.m8n8.x4.shared.b16 {%0,%1,%2,%3}, [%4];" \
                 : "=r"(r0), "=r"(r1), "=r"(r2), "=r"(r3) : "r"(addr))

#define MMA16816(c, a, b0, b1) \
    asm volatile("mma.sync.aligned.m16n8k16.row.col.f32.bf16.bf16.f32 " \
                 "{%0,%1,%2,%3},{%4,%5,%6,%7},{%8,%9},{%0,%1,%2,%3};" \
                 : "+f"((c)[0]), "+f"((c)[1]), "+f"((c)[2]), "+f"((c)[3]) \
                 : "r"((a)[0]), "r"((a)[1]), "r"((a)[2]), "r"((a)[3]), "r"(b0), "r"(b1))

__global__ void __launch_bounds__(THREADS, 1)
cost_main(const float* __restrict__ X, const float* __restrict__ T)
{
    extern __shared__ char dsm[];
    const uint32_t sb = (smem_u32(dsm) + 1023u) & ~1023u;

    const int tid = threadIdx.x;
    const int b   = blockIdx.y;
    const int r   = blockIdx.x;
    const int t0  = (r * NKT) / CTAS_PER_B;
    const int nst = ((r + 1) * NKT) / CTAS_PER_B - t0;

    // zero both stage buffers once (zero rows/cols stay zero forever)
    for (int i = tid; i < (2 * BUF_SZ) / 8; i += THREADS)
        asm volatile("st.shared.b64 [%0], %1;" :: "r"(sb + i * 8), "l"(0ull) : "memory");
    __syncthreads();
    // ones rows: A_x row 100 (-> sum_k t), B row 50 (-> sum_k sigma)
    const uint64_t ones8 = 0x3F803F803F803F80ull;
    if (tid < 16) {
        uint32_t o = SW(100u * 128u + (uint32_t)tid * 8u);
        asm volatile("st.shared.b64 [%0], %1;" :: "r"(sb + o), "l"(ones8) : "memory");
        asm volatile("st.shared.b64 [%0], %1;" :: "r"(sb + BUF_SZ + o), "l"(ones8) : "memory");
    } else if (tid < 32) {
        uint32_t o = SW(50u * 128u + (uint32_t)(tid - 16) * 8u) + 32768u;
        asm volatile("st.shared.b64 [%0], %1;" :: "r"(sb + o), "l"(ones8) : "memory");
        asm volatile("st.shared.b64 [%0], %1;" :: "r"(sb + BUF_SZ + o), "l"(ones8) : "memory");
    }
    __syncthreads();

    const float* Xb = X + (size_t)b * Nq * HWP;
    const float* Tb = T + (size_t)b * Mt * HWP;

    float4 la[4], lb[2];
    auto LOADS = [&](int s) {
        if (s >= nst) return;
        const int kb = (t0 + s) * KS;
        #pragma unroll
        for (int j = 0; j < 4; j++) {
            int idx = tid + THREADS * j;
            if (idx < 1600) {
                int row = idx >> 4, c4 = idx & 15;
                la[j] = *(const float4*)(Xb + (size_t)row * HWP + kb + c4 * 4);
            }
        }
        #pragma unroll
        for (int j = 0; j < 2; j++) {
            int idx = tid + THREADS * j;
            if (idx < 800) {
                int row = idx >> 4, c4 = idx & 15;
                lb[j] = *(const float4*)(Tb + (size_t)row * HWP + kb + c4 * 4);
            }
        }
    };
    LOADS(0);

    // per-warp MMA geometry: 14 active warps, M=112 (7 m16 tiles) x N=56/64
    const int w = tid >> 5, l = tid & 31;
    const bool mma_w = (w < 14);
    const int Rr = (w >> 1) * 16, Cc = (w & 1) * 32;
    const bool full_n = ((w & 1) == 0);    // right half skips cols 56..63 (all-zero)
    const uint32_t rowA  = (uint32_t)(Rr + (l & 15)) * 128u + (uint32_t)(l >> 4) * 16u;
    const uint32_t rowB0 = (uint32_t)(Cc + (l & 15)) * 128u + (uint32_t)(l >> 4) * 16u;
    const uint32_t rowB1 = rowB0 + 16u * 128u;

    float cx[4][4], cs[4][4];
    #pragma unroll
    for (int nb = 0; nb < 4; nb++)
        #pragma unroll
        for (int e = 0; e < 4; e++) { cx[nb][e] = 0.f; cs[nb][e] = 0.f; }

    float ssp[4] = {0.f, 0.f, 0.f, 0.f};   // sum softplus(x)

    for (int s = 0; s < nst; s++) {
        const uint32_t BUF = sb + (uint32_t)(s & 1) * BUF_SZ;
        const uint32_t BTb = BUF + 32768u;

        // ---- convert: fp32 -> (bf16 x, bf16 sigmoid) + softplus partials ----
        #pragma unroll
        for (int j = 0; j < 4; j++) {
            int idx = tid + THREADS * j;
            if (idx < 1600) {
                int row = idx >> 4, c4 = idx & 15;
                float v[4] = {la[j].x, la[j].y, la[j].z, la[j].w};
                float sg[4];
                #pragma unroll
                for (int e = 0; e < 4; e++) {
                    float x = v[e], ea, lg, y;
                    asm("ex2.approx.f32 %0, %1;" : "=f"(ea) : "f"(-1.4426950408889634f * fabsf(x)));
                    float d = 1.f + ea;
                    asm("lg2.approx.f32 %0, %1;" : "=f"(lg) : "f"(d));
                    ssp[j] += fmaf(0.6931471805599453f, lg, fmaxf(x, 0.f));
                    asm("rcp.approx.f32 %0, %1;" : "=f"(y) : "f"(d));
                    sg[e] = (x >= 0.f) ? y : (1.f - y);
                }
                uint32_t xw0, xw1, sw0, sw1;
                asm("cvt.rn.bf16x2.f32 %0, %1, %2;" : "=r"(xw0) : "f"(v[1]),  "f"(v[0]));
                asm("cvt.rn.bf16x2.f32 %0, %1, %2;" : "=r"(xw1) : "f"(v[3]),  "f"(v[2]));
                asm("cvt.rn.bf16x2.f32 %0, %1, %2;" : "=r"(sw0) : "f"(sg[1]), "f"(sg[0]));
                asm("cvt.rn.bf16x2.f32 %0, %1, %2;" : "=r"(sw1) : "f"(sg[3]), "f"(sg[2]));
                uint32_t a = BUF + SW((uint32_t)row * 128u + (uint32_t)c4 * 8u);
                asm volatile("st.shared.v2.b32 [%0], {%1, %2};" :: "r"(a), "r"(xw0), "r"(xw1) : "memory");
                asm volatile("st.shared.v2.b32 [%0], {%1, %2};" :: "r"(a + 16384u), "r"(sw0), "r"(sw1) : "memory");
            }
        }
        #pragma unroll
        for (int j = 0; j < 2; j++) {
            int idx = tid + THREADS * j;
            if (idx < 800) {
                int row = idx >> 4, c4 = idx & 15;
                uint32_t w0, w1;
                asm("cvt.rn.bf16x2.f32 %0, %1, %2;" : "=r"(w0) : "f"(lb[j].y), "f"(lb[j].x));
                asm("cvt.rn.bf16x2.f32 %0, %1, %2;" : "=r"(w1) : "f"(lb[j].w), "f"(lb[j].z));
                uint32_t a = BTb + SW((uint32_t)row * 128u + (uint32_t)c4 * 8u);
                asm volatile("st.shared.v2.b32 [%0], {%1, %2};" :: "r"(a), "r"(w0), "r"(w1) : "memory");
            }
        }
        __syncthreads();

        LOADS(s + 1);   // gmem latency hides under MMA phase

        // ---- mma phase on buffer (s&1) ----
        if (mma_w) {
            #pragma unroll
            for (int i = 0; i < 4; i++) {
                uint32_t aax = BUF + SW(rowA + 32u * i);
                uint32_t ax[4], as[4], q[4], p[4];
                LDSM4(ax[0], ax[1], ax[2], ax[3], aax);
                LDSM4(as[0], as[1], as[2], as[3], aax + 16384u);
                LDSM4(q[0], q[1], q[2], q[3], BTb + SW(rowB0 + 32u * i));
                LDSM4(p[0], p[1], p[2], p[3], BTb + SW(rowB1 + 32u * i));
                MMA16816(cx[0], ax, q[0], q[2]);
                MMA16816(cx[1], ax, q[1], q[3]);
                MMA16816(cx[2], ax, p[0], p[2]);
                MMA16816(cs[0], as, q[0], q[2]);
                MMA16816(cs[1], as, q[1], q[3]);
                MMA16816(cs[2], as, p[0], p[2]);
                if (full_n) {
                    MMA16816(cx[3], ax, p[1], p[3]);
                    MMA16816(cs[3], as, p[1], p[3]);
                }
            }
        }
    }

    // ---- combine: softplus row sums ----
    #pragma unroll
    for (int j = 0; j < 4; j++) {
        int idx = tid + THREADS * j;
        if (idx < 1600)
            atomicAdd(&g_s[OFF_SNSP + b * Nq + (idx >> 4)], ssp[j]);
    }

    // ---- combine: accumulator fragments ----
    auto emit = [&](int rr, int m, float vx, float vs) {
        if (rr < Nq) {
            if (m < Mt) {
                atomicAdd(&g_s[OFF_G1 + (b * Nq + rr) * Mt + m], vx);
                atomicAdd(&g_s[OFF_G2 + (b * Nq + rr) * Mt + m], vs);
            } else if (m == Mt) {
                atomicAdd(&g_s[OFF_SNPM + b * Nq + rr], vs);
            }
        } else if (rr == Nq && m < Mt) {
            atomicAdd(&g_s[OFF_SMT + b * Mt + m], vx);
        }
    };
    if (mma_w) {
        #pragma unroll
        for (int nb = 0; nb < 4; nb++) {
            if (nb == 3 && !full_n) continue;
            const int m0 = Cc + nb * 8 + (l & 3) * 2;
            const int r0 = Rr + (l >> 2);
            emit(r0,     m0,     cx[nb][0], cs[nb][0]);
            emit(r0,     m0 + 1, cx[nb][1], cs[nb][1]);
            emit(r0 + 8, m0,     cx[nb][2], cs[nb][2]);
            emit(r0 + 8, m0 + 1, cx[nb][3], cs[nb][3]);
        }
    }
}

__global__ void cost_epi(const float* __restrict__ logits,
                         const float* __restrict__ style,
                         const int* __restrict__ sids,
                         float* __restrict__ out)
{
    const int n = blockIdx.x, b = blockIdx.y, m = threadIdx.x;
    if (m >= Mt) return;

    const float l0 = logits[(b * Nq + n) * 2 + 0];
    const float l1 = logits[(b * Nq + n) * 2 + 1];
    const float p1 = __fdividef(1.f, 1.f + __expf(l0 - l1));

    const float* st = style + (b * Nq + n) * 4;
    const float s0 = st[0], s1 = st[1], s2 = st[2], s3 = st[3];
    const float mx = fmaxf(fmaxf(s0, s1), fmaxf(s2, s3));
    const float e0 = __expf(s0 - mx), e1 = __expf(s1 - mx);
    const float e2 = __expf(s2 - mx), e3 = __expf(s3 - mx);
    const float inv = __fdividef(1.f, e0 + e1 + e2 + e3);

    const float snsp = g_s[OFF_SNSP + b * Nq + n];
    const float snpm = g_s[OFF_SNPM + b * Nq + n];
    const float G1v  = g_s[OFF_G1 + (b * Nq + n) * Mt + m];
    const float G2v  = g_s[OFF_G2 + (b * Nq + n) * Mt + m];
    const float smt  = g_s[OFF_SMT + b * Mt + m];

    const float cmask = (snsp - G1v) * (1.0f / (float)HWP);
    const float cdice = 1.f - __fdividef(2.f * G2v + 1.f, snpm + smt + 1.f);

    int sid = sids[b * Mt + m];
    sid = sid < 0 ? 0 : (sid > 3 ? 3 : sid);
    float pr = (sid == 0) ? e0 : (sid == 1) ? e1 : (sid == 2) ? e2 : e3;
    pr *= inv;

    float c = -2.f * p1 + 5.f * cmask + 5.f * cdice - pr;
    if (!isfinite(c)) c = isnan(c) ? 10000.f : (c > 0.f ? 10000.f : -10000.f);
    out[(b * Nq + n) * Mt + m] = c;
}

extern "C" void kernel_launch(void* const* d_in, const int* in_sizes, int n_in,
                              void* d_out, int out_size)
{
    const float* pred_logits = (const float*)d_in[0];  // [4,100,2]
    const float* pred_masks  = (const float*)d_in[1];  // [4,100,256,256]
    const float* pred_style  = (const float*)d_in[2];  // [4,100,4]
    const float* tgt_masks   = (const float*)d_in[3];  // [4,50,256,256]
    const int*   styles      = (const int*)d_in[4];    // [4,50]
    float* out = (float*)d_out;                        // [4,100,50]

    cudaFuncSetAttribute(cost_main, cudaFuncAttributeMaxDynamicSharedMemorySize, SMEM_BYTES);

    void* scratch = nullptr;
    cudaGetSymbolAddress(&scratch, g_s);
    cudaMemsetAsync(scratch, 0, SCRATCH_N * sizeof(float), 0);

    dim3 gmain(CTAS_PER_B, Bsz);
    cost_main<<<gmain, THREADS, SMEM_BYTES>>>(pred_masks, tgt_masks);
    dim3 gepi(Nq, Bsz);
    cost_epi<<<gepi, 64>>>(pred_logits, pred_style, styles, out);
}

// round 15
// speedup vs baseline: 1.5297x; 1.0531x over previous
#include <cuda_runtime.h>
#include <cuda_bf16.h>
#include <cstdint>

// ---------------- problem constants ----------------
#define Bsz 4
#define Nq  100
#define Mt  50
#define HWP 65536
#define KS  128                 // k per stage (two 64-col halves)
#define KH  64
#define NKT (HWP / KS)          // 512 stage-tiles per batch
#define CTAS_PER_B 37           // 148 CTAs = one full wave
#define THREADS 512             // 16 warps

// per-stage slot: Ax0 16K | Ax1 16K | As0 16K | As1 16K | Bt0 8K | Bt1 8K = 80K
#define SLOT_SZ 81920
#define SMEM_BYTES (2 * SLOT_SZ + 1024)

// ---------------- fused scratch (one memset) ----------------
#define OFF_G1   0
#define OFF_G2   (Bsz * Nq * Mt)
#define OFF_SNPM (2 * Bsz * Nq * Mt)
#define OFF_SNSP (2 * Bsz * Nq * Mt + Bsz * Nq)
#define OFF_SMT  (2 * Bsz * Nq * Mt + 2 * Bsz * Nq)
#define SCRATCH_N (2 * Bsz * Nq * Mt + 2 * Bsz * Nq + Bsz * Mt)
__device__ float g_s[SCRATCH_N];

__device__ __forceinline__ uint32_t smem_u32(const void* p) {
    uint32_t a;
    asm("{ .reg .u64 t; cvta.to.shared.u64 t, %1; cvt.u32.u64 %0, t; }" : "=r"(a) : "l"(p));
    return a;
}
__device__ __forceinline__ uint32_t SW(uint32_t o) { return o ^ ((o >> 3) & 0x70); }

#define LDSM4(r0, r1, r2, r3, addr) \
    asm volatile("ldmatrix.sync.aligned.m8n8.x4.shared.b16 {%0,%1,%2,%3}, [%4];" \
                 : "=r"(r0), "=r"(r1), "=r"(r2), "=r"(r3) : "r"(addr))

#define MMA16816(c, a, b0, b1) \
    asm volatile("mma.sync.aligned.m16n8k16.row.col.f32.bf16.bf16.f32 " \
                 "{%0,%1,%2,%3},{%4,%5,%6,%7},{%8,%9},{%0,%1,%2,%3};" \
                 : "+f"((c)[0]), "+f"((c)[1]), "+f"((c)[2]), "+f"((c)[3]) \
                 : "r"((a)[0]), "r"((a)[1]), "r"((a)[2]), "r"((a)[3]), "r"(b0), "r"(b1))

__global__ void __launch_bounds__(THREADS, 1)
cost_main(const float* __restrict__ X, const float* __restrict__ T)
{
    extern __shared__ char dsm[];
    const uint32_t sb = (smem_u32(dsm) + 1023u) & ~1023u;

    const int tid = threadIdx.x;
    const int b   = blockIdx.y;
    const int r   = blockIdx.x;
    const int t0  = (r * NKT) / CTAS_PER_B;
    const int nst = ((r + 1) * NKT) / CTAS_PER_B - t0;

    // zero both slots once (rows >=100 of A / >=50 of B stay zero forever)
    for (int i = tid; i < (2 * SLOT_SZ) / 8; i += THREADS)
        asm volatile("st.shared.b64 [%0], %1;" :: "r"(sb + i * 8), "l"(0ull) : "memory");
    __syncthreads();
    // ones: A_x row 100 (both halves) -> sum_k t ; B row 50 (both halves) -> sum_k sigma
    const uint64_t ones8 = 0x3F803F803F803F80ull;
    if (tid < 32) {                 // A_x row 100: 2 halves x 16 chunks of 8B
        int h = tid >> 4, q = tid & 15;
        uint32_t o = (uint32_t)h * 16384u + SW(100u * 128u + (uint32_t)q * 8u);
        asm volatile("st.shared.b64 [%0], %1;" :: "r"(sb + o), "l"(ones8) : "memory");
        asm volatile("st.shared.b64 [%0], %1;" :: "r"(sb + SLOT_SZ + o), "l"(ones8) : "memory");
    } else if (tid < 64) {          // B row 50: 2 halves x 16 chunks of 8B
        int h = (tid >= 48), q = tid & 15;
        uint32_t o = 65536u + (uint32_t)h * 8192u + SW(50u * 128u + (uint32_t)q * 8u);
        asm volatile("st.shared.b64 [%0], %1;" :: "r"(sb + o), "l"(ones8) : "memory");
        asm volatile("st.shared.b64 [%0], %1;" :: "r"(sb + SLOT_SZ + o), "l"(ones8) : "memory");
    }
    __syncthreads();

    const float* Xb = X + (size_t)b * Nq * HWP;
    const float* Tb = T + (size_t)b * Mt * HWP;

    float4 la[4], lb[2];
    auto LOADS = [&](int s, int h) {       // load half (s,h) into regs
        if (s >= nst) return;
        const int kb = (t0 + s) * KS + h * KH;
        #pragma unroll
        for (int j = 0; j < 4; j++) {
            int idx = tid + THREADS * j;
            if (idx < 1600) {                      // 100 rows x 16 float4
                int row = idx >> 4, c4 = idx & 15;
                la[j] = *(const float4*)(Xb + (size_t)row * HWP + kb + c4 * 4);
            }
        }
        #pragma unroll
        for (int j = 0; j < 2; j++) {
            int idx = tid + THREADS * j;
            if (idx < 800) {                       // 50 rows x 16 float4
                int row = idx >> 4, c4 = idx & 15;
                lb[j] = *(const float4*)(Tb + (size_t)row * HWP + kb + c4 * 4);
            }
        }
    };

    float ssp[4] = {0.f, 0.f, 0.f, 0.f};   // sum softplus(x)

    auto CONV = [&](int h, uint32_t BUF) { // regs -> bf16 tiles (half h)
        const uint32_t AXb = BUF + (uint32_t)h * 16384u;
        const uint32_t BTb = BUF + 65536u + (uint32_t)h * 8192u;
        #pragma unroll
        for (int j = 0; j < 4; j++) {
            int idx = tid + THREADS * j;
            if (idx < 1600) {
                int row = idx >> 4, c4 = idx & 15;
                float v[4] = {la[j].x, la[j].y, la[j].z, la[j].w};
                float sg[4];
                #pragma unroll
                for (int e = 0; e < 4; e++) {
                    float x = v[e], ea, lg, y;
                    asm("ex2.approx.f32 %0, %1;" : "=f"(ea) : "f"(-1.4426950408889634f * fabsf(x)));
                    float d = 1.f + ea;
                    asm("lg2.approx.f32 %0, %1;" : "=f"(lg) : "f"(d));
                    ssp[j] += fmaf(0.6931471805599453f, lg, fmaxf(x, 0.f));
                    asm("rcp.approx.f32 %0, %1;" : "=f"(y) : "f"(d));
                    sg[e] = (x >= 0.f) ? y : (1.f - y);
                }
                uint32_t xw0, xw1, sw0, sw1;
                asm("cvt.rn.bf16x2.f32 %0, %1, %2;" : "=r"(xw0) : "f"(v[1]),  "f"(v[0]));
                asm("cvt.rn.bf16x2.f32 %0, %1, %2;" : "=r"(xw1) : "f"(v[3]),  "f"(v[2]));
                asm("cvt.rn.bf16x2.f32 %0, %1, %2;" : "=r"(sw0) : "f"(sg[1]), "f"(sg[0]));
                asm("cvt.rn.bf16x2.f32 %0, %1, %2;" : "=r"(sw1) : "f"(sg[3]), "f"(sg[2]));
                uint32_t a = AXb + SW((uint32_t)row * 128u + (uint32_t)c4 * 8u);
                asm volatile("st.shared.v2.b32 [%0], {%1, %2};" :: "r"(a), "r"(xw0), "r"(xw1) : "memory");
                asm volatile("st.shared.v2.b32 [%0], {%1, %2};" :: "r"(a + 32768u), "r"(sw0), "r"(sw1) : "memory");
            }
        }
        #pragma unroll
        for (int j = 0; j < 2; j++) {
            int idx = tid + THREADS * j;
            if (idx < 800) {
                int row = idx >> 4, c4 = idx & 15;
                uint32_t w0, w1;
                asm("cvt.rn.bf16x2.f32 %0, %1, %2;" : "=r"(w0) : "f"(lb[j].y), "f"(lb[j].x));
                asm("cvt.rn.bf16x2.f32 %0, %1, %2;" : "=r"(w1) : "f"(lb[j].w), "f"(lb[j].z));
                uint32_t a = BTb + SW((uint32_t)row * 128u + (uint32_t)c4 * 8u);
                asm volatile("st.shared.v2.b32 [%0], {%1, %2};" :: "r"(a), "r"(w0), "r"(w1) : "memory");
            }
        }
    };

    // per-warp MMA geometry: 14 warps, M=112 x N=56/64 (zero rows/cols skipped)
    const int w = tid >> 5, l = tid & 31;
    const bool mma_w = (w < 14);
    const int Rr = (w >> 1) * 16, Cc = (w & 1) * 32;
    const bool full_n = ((w & 1) == 0);
    const uint32_t rowA  = (uint32_t)(Rr + (l & 15)) * 128u + (uint32_t)(l >> 4) * 16u;
    const uint32_t rowB0 = (uint32_t)(Cc + (l & 15)) * 128u + (uint32_t)(l >> 4) * 16u;
    const uint32_t rowB1 = rowB0 + 16u * 128u;

    float cx[4][4], cs[4][4];
    #pragma unroll
    for (int nb = 0; nb < 4; nb++)
        #pragma unroll
        for (int e = 0; e < 4; e++) { cx[nb][e] = 0.f; cs[nb][e] = 0.f; }

    auto MMAPH = [&](uint32_t PBUF, int kh) {   // one 64-col half of stage s-1
        if (!mma_w) return;
        const uint32_t AXb = PBUF + (uint32_t)kh * 16384u;
        const uint32_t BTb = PBUF + 65536u + (uint32_t)kh * 8192u;
        #pragma unroll
        for (int i = 0; i < 4; i++) {
            uint32_t ko = 32u * i;
            uint32_t ax[4], as[4], q[4], p[4];
            LDSM4(ax[0], ax[1], ax[2], ax[3], AXb + SW(rowA + ko));
            LDSM4(as[0], as[1], as[2], as[3], AXb + 32768u + SW(rowA + ko));
            LDSM4(q[0], q[1], q[2], q[3], BTb + SW(rowB0 + ko));
            LDSM4(p[0], p[1], p[2], p[3], BTb + SW(rowB1 + ko));
            MMA16816(cx[0], ax, q[0], q[2]);
            MMA16816(cs[0], as, q[0], q[2]);
            MMA16816(cx[1], ax, q[1], q[3]);
            MMA16816(cs[1], as, q[1], q[3]);
            MMA16816(cx[2], ax, p[0], p[2]);
            MMA16816(cs[2], as, p[0], p[2]);
            if (full_n) {
                MMA16816(cx[3], ax, p[1], p[3]);
                MMA16816(cs[3], as, p[1], p[3]);
            }
        }
    };

    // ---- pipelined main loop: MMA(s-1) interleaved between conv halves of s ----
    LOADS(0, 0);
    for (int s = 0; s <= nst; s++) {
        const uint32_t BUF  = sb + (uint32_t)(s & 1) * SLOT_SZ;        // conv target
        const uint32_t PBUF = sb + (uint32_t)((s + 1) & 1) * SLOT_SZ;  // mma source (s-1)
        if (s < nst) { CONV(0, BUF); LOADS(s, 1); }
        if (s > 0)   MMAPH(PBUF, 0);
        if (s < nst) { CONV(1, BUF); LOADS(s + 1, 0); }
        if (s > 0)   MMAPH(PBUF, 1);
        __syncthreads();
    }

    // ---- combine: softplus row sums ----
    #pragma unroll
    for (int j = 0; j < 4; j++) {
        int idx = tid + THREADS * j;
        if (idx < 1600)
            atomicAdd(&g_s[OFF_SNSP + b * Nq + (idx >> 4)], ssp[j]);
    }

    // ---- combine: accumulator fragments ----
    auto emit = [&](int rr, int m, float vx, float vs) {
        if (rr < Nq) {
            if (m < Mt) {
                atomicAdd(&g_s[OFF_G1 + (b * Nq + rr) * Mt + m], vx);
                atomicAdd(&g_s[OFF_G2 + (b * Nq + rr) * Mt + m], vs);
            } else if (m == Mt) {
                atomicAdd(&g_s[OFF_SNPM + b * Nq + rr], vs);
            }
        } else if (rr == Nq && m < Mt) {
            atomicAdd(&g_s[OFF_SMT + b * Mt + m], vx);
        }
    };
    if (mma_w) {
        #pragma unroll
        for (int nb = 0; nb < 4; nb++) {
            if (nb == 3 && !full_n) continue;
            const int m0 = Cc + nb * 8 + (l & 3) * 2;
            const int r0 = Rr + (l >> 2);
            emit(r0,     m0,     cx[nb][0], cs[nb][0]);
            emit(r0,     m0 + 1, cx[nb][1], cs[nb][1]);
            emit(r0 + 8, m0,     cx[nb][2], cs[nb][2]);
            emit(r0 + 8, m0 + 1, cx[nb][3], cs[nb][3]);
        }
    }
}

__global__ void cost_epi(const float* __restrict__ logits,
                         const float* __restrict__ style,
                         const int* __restrict__ sids,
                         float* __restrict__ out)
{
    const int n = blockIdx.x, b = blockIdx.y, m = threadIdx.x;
    if (m >= Mt) return;

    const float l0 = logits[(b * Nq + n) * 2 + 0];
    const float l1 = logits[(b * Nq + n) * 2 + 1];
    const float p1 = __fdividef(1.f, 1.f + __expf(l0 - l1));

    const float* st = style + (b * Nq + n) * 4;
    const float s0 = st[0], s1 = st[1], s2 = st[2], s3 = st[3];
    const float mx = fmaxf(fmaxf(s0, s1), fmaxf(s2, s3));
    const float e0 = __expf(s0 - mx), e1 = __expf(s1 - mx);
    const float e2 = __expf(s2 - mx), e3 = __expf(s3 - mx);
    const float inv = __fdividef(1.f, e0 + e1 + e2 + e3);

    const float snsp = g_s[OFF_SNSP + b * Nq + n];
    const float snpm = g_s[OFF_SNPM + b * Nq + n];
    const float G1v  = g_s[OFF_G1 + (b * Nq + n) * Mt + m];
    const float G2v  = g_s[OFF_G2 + (b * Nq + n) * Mt + m];
    const float smt  = g_s[OFF_SMT + b * Mt + m];

    const float cmask = (snsp - G1v) * (1.0f / (float)HWP);
    const float cdice = 1.f - __fdividef(2.f * G2v + 1.f, snpm + smt + 1.f);

    int sid = sids[b * Mt + m];
    sid = sid < 0 ? 0 : (sid > 3 ? 3 : sid);
    float pr = (sid == 0) ? e0 : (sid == 1) ? e1 : (sid == 2) ? e2 : e3;
    pr *= inv;

    float c = -2.f * p1 + 5.f * cmask + 5.f * cdice - pr;
    if (!isfinite(c)) c = isnan(c) ? 10000.f : (c > 0.f ? 10000.f : -10000.f);
    out[(b * Nq + n) * Mt + m] = c;
}

extern "C" void kernel_launch(void* const* d_in, const int* in_sizes, int n_in,
                              void* d_out, int out_size)
{
    const float* pred_logits = (const float*)d_in[0];  // [4,100,2]
    const float* pred_masks  = (const float*)d_in[1];  // [4,100,256,256]
    const float* pred_style  = (const float*)d_in[2];  // [4,100,4]
    const float* tgt_masks   = (const float*)d_in[3];  // [4,50,256,256]
    const int*   styles      = (const int*)d_in[4];    // [4,50]
    float* out = (float*)d_out;                        // [4,100,50]

    cudaFuncSetAttribute(cost_main, cudaFuncAttributeMaxDynamicSharedMemorySize, SMEM_BYTES);

    void* scratch = nullptr;
    cudaGetSymbolAddress(&scratch, g_s);
    cudaMemsetAsync(scratch, 0, SCRATCH_N * sizeof(float), 0);

    dim3 gmain(CTAS_PER_B, Bsz);
    cost_main<<<gmain, THREADS, SMEM_BYTES>>>(pred_masks, tgt_masks);
    dim3 gepi(Nq, Bsz);
    cost_epi<<<gepi, 64>>>(pred_logits, pred_style, styles, out);
}

// round 16
// speedup vs baseline: 1.6328x; 1.0674x over previous
#include <cuda_runtime.h>
#include <cuda_bf16.h>
#include <cstdint>

// ---------------- problem constants ----------------
#define Bsz 4
#define Nq  100
#define Mt  50
#define HWP 65536
#define KS  128                 // k per stage (two 64-col halves)
#define KH  64
#define NKT (HWP / KS)          // 512 stage-tiles per batch
#define CTAS_PER_B 37           // 148 CTAs = one full wave
#define THREADS 512             // 16 warps

// per-stage slot: Ax0 16K | Ax1 16K | As0 16K | As1 16K | Bt0 8K | Bt1 8K = 80K
#define SLOT_SZ 81920
#define SMEM_BYTES (2 * SLOT_SZ + 1024)

// ---------------- fused scratch (one memset) ----------------
#define OFF_G1   0
#define OFF_G2   (Bsz * Nq * Mt)
#define OFF_SNPM (2 * Bsz * Nq * Mt)
#define OFF_SNSP (2 * Bsz * Nq * Mt + Bsz * Nq)
#define OFF_SMT  (2 * Bsz * Nq * Mt + 2 * Bsz * Nq)
#define SCRATCH_N (2 * Bsz * Nq * Mt + 2 * Bsz * Nq + Bsz * Mt)
__device__ float g_s[SCRATCH_N];

__device__ __forceinline__ uint32_t smem_u32(const void* p) {
    uint32_t a;
    asm("{ .reg .u64 t; cvta.to.shared.u64 t, %1; cvt.u32.u64 %0, t; }" : "=r"(a) : "l"(p));
    return a;
}
__device__ __forceinline__ uint32_t SW(uint32_t o) { return o ^ ((o >> 3) & 0x70); }

#define LDSM4(r0, r1, r2, r3, addr) \
    asm volatile("ldmatrix.sync.aligned.m8n8.x4.shared.b16 {%0,%1,%2,%3}, [%4];" \
                 : "=r"(r0), "=r"(r1), "=r"(r2), "=r"(r3) : "r"(addr))

#define MMA16816(c, a, b0, b1) \
    asm volatile("mma.sync.aligned.m16n8k16.row.col.f32.bf16.bf16.f32 " \
                 "{%0,%1,%2,%3},{%4,%5,%6,%7},{%8,%9},{%0,%1,%2,%3};" \
                 : "+f"((c)[0]), "+f"((c)[1]), "+f"((c)[2]), "+f"((c)[3]) \
                 : "r"((a)[0]), "r"((a)[1]), "r"((a)[2]), "r"((a)[3]), "r"(b0), "r"(b1))

__global__ void __launch_bounds__(THREADS, 1)
cost_main(const float* __restrict__ X, const float* __restrict__ T)
{
    extern __shared__ char dsm[];
    const uint32_t sb = (smem_u32(dsm) + 1023u) & ~1023u;

    const int tid = threadIdx.x;
    const int b   = blockIdx.y;
    const int r   = blockIdx.x;
    const int t0  = (r * NKT) / CTAS_PER_B;
    const int nst = ((r + 1) * NKT) / CTAS_PER_B - t0;

    // zero both slots once (rows >=100 of A / >=50 of B stay zero forever)
    for (int i = tid; i < (2 * SLOT_SZ) / 8; i += THREADS)
        asm volatile("st.shared.b64 [%0], %1;" :: "r"(sb + i * 8), "l"(0ull) : "memory");
    __syncthreads();
    // ones: A_x row 100 (both halves) -> sum_k t ; B row 50 (both halves) -> sum_k sigma
    const uint64_t ones8 = 0x3F803F803F803F80ull;
    if (tid < 32) {                 // A_x row 100: 2 halves x 16 chunks of 8B
        int h = tid >> 4, q = tid & 15;
        uint32_t o = (uint32_t)h * 16384u + SW(100u * 128u + (uint32_t)q * 8u);
        asm volatile("st.shared.b64 [%0], %1;" :: "r"(sb + o), "l"(ones8) : "memory");
        asm volatile("st.shared.b64 [%0], %1;" :: "r"(sb + SLOT_SZ + o), "l"(ones8) : "memory");
    } else if (tid < 64) {          // B row 50: 2 halves x 16 chunks of 8B
        int h = (tid >= 48), q = tid & 15;
        uint32_t o = 65536u + (uint32_t)h * 8192u + SW(50u * 128u + (uint32_t)q * 8u);
        asm volatile("st.shared.b64 [%0], %1;" :: "r"(sb + o), "l"(ones8) : "memory");
        asm volatile("st.shared.b64 [%0], %1;" :: "r"(sb + SLOT_SZ + o), "l"(ones8) : "memory");
    }
    __syncthreads();

    const float* Xb = X + (size_t)b * Nq * HWP;
    const float* Tb = T + (size_t)b * Mt * HWP;

    float4 la[4], lb[2];
    auto LOADS = [&](int s, int h) {       // load half (s,h) into regs
        if (s >= nst) return;
        const int kb = (t0 + s) * KS + h * KH;
        #pragma unroll
        for (int j = 0; j < 4; j++) {
            int idx = tid + THREADS * j;
            if (idx < 1600) {                      // 100 rows x 16 float4
                int row = idx >> 4, c4 = idx & 15;
                la[j] = *(const float4*)(Xb + (size_t)row * HWP + kb + c4 * 4);
            }
        }
        #pragma unroll
        for (int j = 0; j < 2; j++) {
            int idx = tid + THREADS * j;
            if (idx < 800) {                       // 50 rows x 16 float4
                int row = idx >> 4, c4 = idx & 15;
                lb[j] = *(const float4*)(Tb + (size_t)row * HWP + kb + c4 * 4);
            }
        }
    };

    float spm[4] = {0.f, 0.f, 0.f, 0.f};   // sum relu(x)
    float prd[4] = {1.f, 1.f, 1.f, 1.f};   // prod sigma(|x|)  (>= 2^-112, no underflow)

    auto CONV = [&](int h, uint32_t BUF) { // regs -> bf16 tiles (half h)
        const uint32_t AXb = BUF + (uint32_t)h * 16384u;
        const uint32_t BTb = BUF + 65536u + (uint32_t)h * 8192u;
        #pragma unroll
        for (int j = 0; j < 4; j++) {
            int idx = tid + THREADS * j;
            if (idx < 1600) {
                int row = idx >> 4, c4 = idx & 15;
                float v[4] = {la[j].x, la[j].y, la[j].z, la[j].w};
                float sg[4];
                #pragma unroll
                for (int e = 0; e < 4; e++) {
                    float x = v[e], th;
                    asm("tanh.approx.f32 %0, %1;" : "=f"(th) : "f"(0.5f * fabsf(x)));
                    float sm = fmaf(0.5f, th, 0.5f);        // sigma(|x|) in [0.5, 1)
                    spm[j] += fmaxf(x, 0.f);
                    prd[j] *= sm;
                    sg[e] = (x >= 0.f) ? sm : (1.f - sm);
                }
                uint32_t xw0, xw1, sw0, sw1;
                asm("cvt.rn.bf16x2.f32 %0, %1, %2;" : "=r"(xw0) : "f"(v[1]),  "f"(v[0]));
                asm("cvt.rn.bf16x2.f32 %0, %1, %2;" : "=r"(xw1) : "f"(v[3]),  "f"(v[2]));
                asm("cvt.rn.bf16x2.f32 %0, %1, %2;" : "=r"(sw0) : "f"(sg[1]), "f"(sg[0]));
                asm("cvt.rn.bf16x2.f32 %0, %1, %2;" : "=r"(sw1) : "f"(sg[3]), "f"(sg[2]));
                uint32_t a = AXb + SW((uint32_t)row * 128u + (uint32_t)c4 * 8u);
                asm volatile("st.shared.v2.b32 [%0], {%1, %2};" :: "r"(a), "r"(xw0), "r"(xw1) : "memory");
                asm volatile("st.shared.v2.b32 [%0], {%1, %2};" :: "r"(a + 32768u), "r"(sw0), "r"(sw1) : "memory");
            }
        }
        #pragma unroll
        for (int j = 0; j < 2; j++) {
            int idx = tid + THREADS * j;
            if (idx < 800) {
                int row = idx >> 4, c4 = idx & 15;
                uint32_t w0, w1;
                asm("cvt.rn.bf16x2.f32 %0, %1, %2;" : "=r"(w0) : "f"(lb[j].y), "f"(lb[j].x));
                asm("cvt.rn.bf16x2.f32 %0, %1, %2;" : "=r"(w1) : "f"(lb[j].w), "f"(lb[j].z));
                uint32_t a = BTb + SW((uint32_t)row * 128u + (uint32_t)c4 * 8u);
                asm volatile("st.shared.v2.b32 [%0], {%1, %2};" :: "r"(a), "r"(w0), "r"(w1) : "memory");
            }
        }
    };

    // per-warp MMA geometry: 14 warps, M=112 x N=56/64 (zero rows/cols skipped)
    const int w = tid >> 5, l = tid & 31;
    const bool mma_w = (w < 14);
    const int Rr = (w >> 1) * 16, Cc = (w & 1) * 32;
    const bool full_n = ((w & 1) == 0);
    const uint32_t rowA  = (uint32_t)(Rr + (l & 15)) * 128u + (uint32_t)(l >> 4) * 16u;
    const uint32_t rowB0 = (uint32_t)(Cc + (l & 15)) * 128u + (uint32_t)(l >> 4) * 16u;
    const uint32_t rowB1 = rowB0 + 16u * 128u;

    float cx[4][4], cs[4][4];
    #pragma unroll
    for (int nb = 0; nb < 4; nb++)
        #pragma unroll
        for (int e = 0; e < 4; e++) { cx[nb][e] = 0.f; cs[nb][e] = 0.f; }

    auto MMAPH = [&](uint32_t PBUF, int kh) {   // one 64-col half of stage s-1
        if (!mma_w) return;
        const uint32_t AXb = PBUF + (uint32_t)kh * 16384u;
        const uint32_t BTb = PBUF + 65536u + (uint32_t)kh * 8192u;
        #pragma unroll
        for (int i = 0; i < 4; i++) {
            uint32_t ko = 32u * i;
            uint32_t ax[4], as[4], q[4], p[4];
            LDSM4(ax[0], ax[1], ax[2], ax[3], AXb + SW(rowA + ko));
            LDSM4(as[0], as[1], as[2], as[3], AXb + 32768u + SW(rowA + ko));
            LDSM4(q[0], q[1], q[2], q[3], BTb + SW(rowB0 + ko));
            LDSM4(p[0], p[1], p[2], p[3], BTb + SW(rowB1 + ko));
            MMA16816(cx[0], ax, q[0], q[2]);
            MMA16816(cs[0], as, q[0], q[2]);
            MMA16816(cx[1], ax, q[1], q[3]);
            MMA16816(cs[1], as, q[1], q[3]);
            MMA16816(cx[2], ax, p[0], p[2]);
            MMA16816(cs[2], as, p[0], p[2]);
            if (full_n) {
                MMA16816(cx[3], ax, p[1], p[3]);
                MMA16816(cs[3], as, p[1], p[3]);
            }
        }
    };

    // ---- pipelined main loop: MMA(s-1) interleaved between conv halves of s ----
    LOADS(0, 0);
    for (int s = 0; s <= nst; s++) {
        const uint32_t BUF  = sb + (uint32_t)(s & 1) * SLOT_SZ;        // conv target
        const uint32_t PBUF = sb + (uint32_t)((s + 1) & 1) * SLOT_SZ;  // mma source (s-1)
        if (s < nst) { CONV(0, BUF); LOADS(s, 1); }
        if (s > 0)   MMAPH(PBUF, 0);
        if (s < nst) { CONV(1, BUF); LOADS(s + 1, 0); }
        if (s > 0)   MMAPH(PBUF, 1);
        __syncthreads();
    }

    // ---- combine: softplus row sums  (sum softplus = sum relu - ln(prod sigma(|x|))) ----
    #pragma unroll
    for (int j = 0; j < 4; j++) {
        int idx = tid + THREADS * j;
        if (idx < 1600) {
            float lg;
            asm("lg2.approx.f32 %0, %1;" : "=f"(lg) : "f"(prd[j]));
            atomicAdd(&g_s[OFF_SNSP + b * Nq + (idx >> 4)],
                      fmaf(-0.6931471805599453f, lg, spm[j]));
        }
    }

    // ---- combine: accumulator fragments ----
    auto emit = [&](int rr, int m, float vx, float vs) {
        if (rr < Nq) {
            if (m < Mt) {
                atomicAdd(&g_s[OFF_G1 + (b * Nq + rr) * Mt + m], vx);
                atomicAdd(&g_s[OFF_G2 + (b * Nq + rr) * Mt + m], vs);
            } else if (m == Mt) {
                atomicAdd(&g_s[OFF_SNPM + b * Nq + rr], vs);
            }
        } else if (rr == Nq && m < Mt) {
            atomicAdd(&g_s[OFF_SMT + b * Mt + m], vx);
        }
    };
    if (mma_w) {
        #pragma unroll
        for (int nb = 0; nb < 4; nb++) {
            if (nb == 3 && !full_n) continue;
            const int m0 = Cc + nb * 8 + (l & 3) * 2;
            const int r0 = Rr + (l >> 2);
            emit(r0,     m0,     cx[nb][0], cs[nb][0]);
            emit(r0,     m0 + 1, cx[nb][1], cs[nb][1]);
            emit(r0 + 8, m0,     cx[nb][2], cs[nb][2]);
            emit(r0 + 8, m0 + 1, cx[nb][3], cs[nb][3]);
        }
    }
}

__global__ void cost_epi(const float* __restrict__ logits,
                         const float* __restrict__ style,
                         const int* __restrict__ sids,
                         float* __restrict__ out)
{
    const int n = blockIdx.x, b = blockIdx.y, m = threadIdx.x;
    if (m >= Mt) return;

    const float l0 = logits[(b * Nq + n) * 2 + 0];
    const float l1 = logits[(b * Nq + n) * 2 + 1];
    const float p1 = __fdividef(1.f, 1.f + __expf(l0 - l1));

    const float* st = style + (b * Nq + n) * 4;
    const float s0 = st[0], s1 = st[1], s2 = st[2], s3 = st[3];
    const float mx = fmaxf(fmaxf(s0, s1), fmaxf(s2, s3));
    const float e0 = __expf(s0 - mx), e1 = __expf(s1 - mx);
    const float e2 = __expf(s2 - mx), e3 = __expf(s3 - mx);
    const float inv = __fdividef(1.f, e0 + e1 + e2 + e3);

    const float snsp = g_s[OFF_SNSP + b * Nq + n];
    const float snpm = g_s[OFF_SNPM + b * Nq + n];
    const float G1v  = g_s[OFF_G1 + (b * Nq + n) * Mt + m];
    const float G2v  = g_s[OFF_G2 + (b * Nq + n) * Mt + m];
    const float smt  = g_s[OFF_SMT + b * Mt + m];

    const float cmask = (snsp - G1v) * (1.0f / (float)HWP);
    const float cdice = 1.f - __fdividef(2.f * G2v + 1.f, snpm + smt + 1.f);

    int sid = sids[b * Mt + m];
    sid = sid < 0 ? 0 : (sid > 3 ? 3 : sid);
    float pr = (sid == 0) ? e0 : (sid == 1) ? e1 : (sid == 2) ? e2 : e3;
    pr *= inv;

    float c = -2.f * p1 + 5.f * cmask + 5.f * cdice - pr;
    if (!isfinite(c)) c = isnan(c) ? 10000.f : (c > 0.f ? 10000.f : -10000.f);
    out[(b * Nq + n) * Mt + m] = c;
}

extern "C" void kernel_launch(void* const* d_in, const int* in_sizes, int n_in,
                              void* d_out, int out_size)
{
    const float* pred_logits = (const float*)d_in[0];  // [4,100,2]
    const float* pred_masks  = (const float*)d_in[1];  // [4,100,256,256]
    const float* pred_style  = (const float*)d_in[2];  // [4,100,4]
    const float* tgt_masks   = (const float*)d_in[3];  // [4,50,256,256]
    const int*   styles      = (const int*)d_in[4];    // [4,50]
    float* out = (float*)d_out;                        // [4,100,50]

    cudaFuncSetAttribute(cost_main, cudaFuncAttributeMaxDynamicSharedMemorySize, SMEM_BYTES);

    void* scratch = nullptr;
    cudaGetSymbolAddress(&scratch, g_s);
    cudaMemsetAsync(scratch, 0, SCRATCH_N * sizeof(float), 0);

    dim3 gmain(CTAS_PER_B, Bsz);
    cost_main<<<gmain, THREADS, SMEM_BYTES>>>(pred_masks, tgt_masks);
    dim3 gepi(Nq, Bsz);
    cost_epi<<<gepi, 64>>>(pred_logits, pred_style, styles, out);
}

// round 17
// speedup vs baseline: 1.6800x; 1.0289x over previous
#include <cuda_runtime.h>
#include <cuda_bf16.h>
#include <cstdint>

// ---------------- problem constants ----------------
#define Bsz 4
#define Nq  100
#define Mt  50
#define HWP 65536
#define KS  128                 // k per stage (two 64-col halves)
#define KH  64
#define NKT (HWP / KS)          // 512 stage-tiles per batch
#define CTAS_PER_B 37           // 148 CTAs = one full wave
#define THREADS 512             // 16 warps

// per-stage slot: Ax0 16K | Ax1 16K | As0 16K | As1 16K | Bt0 8K | Bt1 8K = 80K
#define SLOT_SZ 81920
#define SMEM_BYTES (2 * SLOT_SZ + 1024)

// ---------------- fused scratch (one memset) ----------------
#define OFF_G1   0
#define OFF_G2   (Bsz * Nq * Mt)
#define OFF_SNPM (2 * Bsz * Nq * Mt)
#define OFF_SNSP (2 * Bsz * Nq * Mt + Bsz * Nq)
#define OFF_SMT  (2 * Bsz * Nq * Mt + 2 * Bsz * Nq)
#define SCRATCH_N (2 * Bsz * Nq * Mt + 2 * Bsz * Nq + Bsz * Mt)
__device__ float g_s[SCRATCH_N];

__device__ __forceinline__ uint32_t smem_u32(const void* p) {
    uint32_t a;
    asm("{ .reg .u64 t; cvta.to.shared.u64 t, %1; cvt.u32.u64 %0, t; }" : "=r"(a) : "l"(p));
    return a;
}
__device__ __forceinline__ uint32_t SW(uint32_t o) { return o ^ ((o >> 3) & 0x70); }

#define LDSM4(r0, r1, r2, r3, addr) \
    asm volatile("ldmatrix.sync.aligned.m8n8.x4.shared.b16 {%0,%1,%2,%3}, [%4];" \
                 : "=r"(r0), "=r"(r1), "=r"(r2), "=r"(r3) : "r"(addr))

#define MMA16816(c, a, b0, b1) \
    asm volatile("mma.sync.aligned.m16n8k16.row.col.f32.bf16.bf16.f32 " \
                 "{%0,%1,%2,%3},{%4,%5,%6,%7},{%8,%9},{%0,%1,%2,%3};" \
                 : "+f"((c)[0]), "+f"((c)[1]), "+f"((c)[2]), "+f"((c)[3]) \
                 : "r"((a)[0]), "r"((a)[1]), "r"((a)[2]), "r"((a)[3]), "r"(b0), "r"(b1))

__global__ void __launch_bounds__(THREADS, 1)
cost_main(const float* __restrict__ X, const float* __restrict__ T)
{
    extern __shared__ char dsm[];
    const uint32_t sb = (smem_u32(dsm) + 1023u) & ~1023u;

    const int tid = threadIdx.x;
    const int b   = blockIdx.y;
    const int r   = blockIdx.x;
    const int t0  = (r * NKT) / CTAS_PER_B;
    const int nst = ((r + 1) * NKT) / CTAS_PER_B - t0;

    // zero both slots once (rows >=100 of A / >=50 of B stay zero forever)
    for (int i = tid; i < (2 * SLOT_SZ) / 8; i += THREADS)
        asm volatile("st.shared.b64 [%0], %1;" :: "r"(sb + i * 8), "l"(0ull) : "memory");
    __syncthreads();
    // ones: A_x row 100 (both halves) -> sum_k t ; B row 50 (both halves) -> sum_k sigma
    const uint64_t ones8 = 0x3F803F803F803F80ull;
    if (tid < 32) {                 // A_x row 100: 2 halves x 16 chunks of 8B
        int h = tid >> 4, q = tid & 15;
        uint32_t o = (uint32_t)h * 16384u + SW(100u * 128u + (uint32_t)q * 8u);
        asm volatile("st.shared.b64 [%0], %1;" :: "r"(sb + o), "l"(ones8) : "memory");
        asm volatile("st.shared.b64 [%0], %1;" :: "r"(sb + SLOT_SZ + o), "l"(ones8) : "memory");
    } else if (tid < 64) {          // B row 50: 2 halves x 16 chunks of 8B
        int h = (tid >= 48), q = tid & 15;
        uint32_t o = 65536u + (uint32_t)h * 8192u + SW(50u * 128u + (uint32_t)q * 8u);
        asm volatile("st.shared.b64 [%0], %1;" :: "r"(sb + o), "l"(ones8) : "memory");
        asm volatile("st.shared.b64 [%0], %1;" :: "r"(sb + SLOT_SZ + o), "l"(ones8) : "memory");
    }
    __syncthreads();

    const float* Xb = X + (size_t)b * Nq * HWP;
    const float* Tb = T + (size_t)b * Mt * HWP;

    float4 la[4], lb[2];
    auto LOADS = [&](int s, int h) {       // load half (s,h) into regs
        if (s >= nst) return;
        const int kb = (t0 + s) * KS + h * KH;
        #pragma unroll
        for (int j = 0; j < 4; j++) {
            int idx = tid + THREADS * j;
            if (idx < 1600) {                      // 100 rows x 16 float4
                int row = idx >> 4, c4 = idx & 15;
                la[j] = *(const float4*)(Xb + (size_t)row * HWP + kb + c4 * 4);
            }
        }
        #pragma unroll
        for (int j = 0; j < 2; j++) {
            int idx = tid + THREADS * j;
            if (idx < 800) {                       // 50 rows x 16 float4
                int row = idx >> 4, c4 = idx & 15;
                lb[j] = *(const float4*)(Tb + (size_t)row * HWP + kb + c4 * 4);
            }
        }
    };

    float spm[4] = {0.f, 0.f, 0.f, 0.f};   // sum relu(x)
    float prd[4] = {1.f, 1.f, 1.f, 1.f};   // prod sigma(|x|)  (>= 2^-112, no underflow)

    auto CONV = [&](int h, uint32_t BUF) { // regs -> bf16 tiles (half h)
        const uint32_t AXb = BUF + (uint32_t)h * 16384u;
        const uint32_t BTb = BUF + 65536u + (uint32_t)h * 8192u;
        #pragma unroll
        for (int j = 0; j < 4; j++) {
            int idx = tid + THREADS * j;
            if (idx < 1600) {
                int row = idx >> 4, c4 = idx & 15;
                float v[4] = {la[j].x, la[j].y, la[j].z, la[j].w};
                float sg[4];
                #pragma unroll
                for (int e = 0; e < 4; e++) {
                    float x = v[e], th;
                    asm("tanh.approx.f32 %0, %1;" : "=f"(th) : "f"(0.5f * x));
                    sg[e] = fmaf(0.5f, th, 0.5f);               // sigma(x), no select
                    spm[j] += fmaxf(x, 0.f);
                    prd[j] *= fmaf(0.5f, fabsf(th), 0.5f);      // sigma(|x|)
                }
                uint32_t xw0, xw1, sw0, sw1;
                asm("cvt.rn.bf16x2.f32 %0, %1, %2;" : "=r"(xw0) : "f"(v[1]),  "f"(v[0]));
                asm("cvt.rn.bf16x2.f32 %0, %1, %2;" : "=r"(xw1) : "f"(v[3]),  "f"(v[2]));
                asm("cvt.rn.bf16x2.f32 %0, %1, %2;" : "=r"(sw0) : "f"(sg[1]), "f"(sg[0]));
                asm("cvt.rn.bf16x2.f32 %0, %1, %2;" : "=r"(sw1) : "f"(sg[3]), "f"(sg[2]));
                uint32_t a = AXb + SW((uint32_t)row * 128u + (uint32_t)c4 * 8u);
                asm volatile("st.shared.v2.b32 [%0], {%1, %2};" :: "r"(a), "r"(xw0), "r"(xw1) : "memory");
                asm volatile("st.shared.v2.b32 [%0], {%1, %2};" :: "r"(a + 32768u), "r"(sw0), "r"(sw1) : "memory");
            }
        }
        #pragma unroll
        for (int j = 0; j < 2; j++) {
            int idx = tid + THREADS * j;
            if (idx < 800) {
                int row = idx >> 4, c4 = idx & 15;
                uint32_t w0, w1;
                asm("cvt.rn.bf16x2.f32 %0, %1, %2;" : "=r"(w0) : "f"(lb[j].y), "f"(lb[j].x));
                asm("cvt.rn.bf16x2.f32 %0, %1, %2;" : "=r"(w1) : "f"(lb[j].w), "f"(lb[j].z));
                uint32_t a = BTb + SW((uint32_t)row * 128u + (uint32_t)c4 * 8u);
                asm volatile("st.shared.v2.b32 [%0], {%1, %2};" :: "r"(a), "r"(w0), "r"(w1) : "memory");
            }
        }
    };

    // per-warp MMA geometry: 14 warps, M=112 x N=56/64 (zero rows/cols skipped)
    const int w = tid >> 5, l = tid & 31;
    const bool mma_w = (w < 14);
    const int Rr = (w >> 1) * 16, Cc = (w & 1) * 32;
    const bool full_n = ((w & 1) == 0);
    const uint32_t rowA  = (uint32_t)(Rr + (l & 15)) * 128u + (uint32_t)(l >> 4) * 16u;
    const uint32_t rowB0 = (uint32_t)(Cc + (l & 15)) * 128u + (uint32_t)(l >> 4) * 16u;
    const uint32_t rowB1 = rowB0 + 16u * 128u;

    float cx[4][4], cs[4][4];
    #pragma unroll
    for (int nb = 0; nb < 4; nb++)
        #pragma unroll
        for (int e = 0; e < 4; e++) { cx[nb][e] = 0.f; cs[nb][e] = 0.f; }

    auto MMAPH = [&](uint32_t PBUF, int kh) {   // one 64-col half of stage s-1
        if (!mma_w) return;
        const uint32_t AXb = PBUF + (uint32_t)kh * 16384u;
        const uint32_t BTb = PBUF + 65536u + (uint32_t)kh * 8192u;
        #pragma unroll
        for (int i = 0; i < 4; i++) {
            uint32_t ko = 32u * i;
            uint32_t ax[4], as[4], q[4], p[4];
            LDSM4(ax[0], ax[1], ax[2], ax[3], AXb + SW(rowA + ko));
            LDSM4(as[0], as[1], as[2], as[3], AXb + 32768u + SW(rowA + ko));
            LDSM4(q[0], q[1], q[2], q[3], BTb + SW(rowB0 + ko));
            LDSM4(p[0], p[1], p[2], p[3], BTb + SW(rowB1 + ko));
            MMA16816(cx[0], ax, q[0], q[2]);
            MMA16816(cs[0], as, q[0], q[2]);
            MMA16816(cx[1], ax, q[1], q[3]);
            MMA16816(cs[1], as, q[1], q[3]);
            MMA16816(cx[2], ax, p[0], p[2]);
            MMA16816(cs[2], as, p[0], p[2]);
            if (full_n) {
                MMA16816(cx[3], ax, p[1], p[3]);
                MMA16816(cs[3], as, p[1], p[3]);
            }
        }
    };

    // ---- pipelined main loop: MMA(s-1) interleaved between conv halves of s ----
    LOADS(0, 0);
    for (int s = 0; s <= nst; s++) {
        const uint32_t BUF  = sb + (uint32_t)(s & 1) * SLOT_SZ;        // conv target
        const uint32_t PBUF = sb + (uint32_t)((s + 1) & 1) * SLOT_SZ;  // mma source (s-1)
        if (s < nst) { CONV(0, BUF); LOADS(s, 1); }
        if (s > 0)   MMAPH(PBUF, 0);
        if (s < nst) { CONV(1, BUF); LOADS(s + 1, 0); }
        if (s > 0)   MMAPH(PBUF, 1);
        __syncthreads();
    }

    // ---- combine: softplus row sums  (sum softplus = sum relu - ln(prod sigma(|x|))) ----
    #pragma unroll
    for (int j = 0; j < 4; j++) {
        int idx = tid + THREADS * j;
        if (idx < 1600) {
            float lg;
            asm("lg2.approx.f32 %0, %1;" : "=f"(lg) : "f"(prd[j]));
            atomicAdd(&g_s[OFF_SNSP + b * Nq + (idx >> 4)],
                      fmaf(-0.6931471805599453f, lg, spm[j]));
        }
    }

    // ---- combine: accumulator fragments ----
    auto emit = [&](int rr, int m, float vx, float vs) {
        if (rr < Nq) {
            if (m < Mt) {
                atomicAdd(&g_s[OFF_G1 + (b * Nq + rr) * Mt + m], vx);
                atomicAdd(&g_s[OFF_G2 + (b * Nq + rr) * Mt + m], vs);
            } else if (m == Mt) {
                atomicAdd(&g_s[OFF_SNPM + b * Nq + rr], vs);
            }
        } else if (rr == Nq && m < Mt) {
            atomicAdd(&g_s[OFF_SMT + b * Mt + m], vx);
        }
    };
    if (mma_w) {
        #pragma unroll
        for (int nb = 0; nb < 4; nb++) {
            if (nb == 3 && !full_n) continue;
            const int m0 = Cc + nb * 8 + (l & 3) * 2;
            const int r0 = Rr + (l >> 2);
            emit(r0,     m0,     cx[nb][0], cs[nb][0]);
            emit(r0,     m0 + 1, cx[nb][1], cs[nb][1]);
            emit(r0 + 8, m0,     cx[nb][2], cs[nb][2]);
            emit(r0 + 8, m0 + 1, cx[nb][3], cs[nb][3]);
        }
    }
}

__global__ void cost_epi(const float* __restrict__ logits,
                         const float* __restrict__ style,
                         const int* __restrict__ sids,
                         float* __restrict__ out)
{
    const int n = blockIdx.x, b = blockIdx.y, m = threadIdx.x;
    if (m >= Mt) return;

    const float l0 = logits[(b * Nq + n) * 2 + 0];
    const float l1 = logits[(b * Nq + n) * 2 + 1];
    const float p1 = __fdividef(1.f, 1.f + __expf(l0 - l1));

    const float* st = style + (b * Nq + n) * 4;
    const float s0 = st[0], s1 = st[1], s2 = st[2], s3 = st[3];
    const float mx = fmaxf(fmaxf(s0, s1), fmaxf(s2, s3));
    const float e0 = __expf(s0 - mx), e1 = __expf(s1 - mx);
    const float e2 = __expf(s2 - mx), e3 = __expf(s3 - mx);
    const float inv = __fdividef(1.f, e0 + e1 + e2 + e3);

    const float snsp = g_s[OFF_SNSP + b * Nq + n];
    const float snpm = g_s[OFF_SNPM + b * Nq + n];
    const float G1v  = g_s[OFF_G1 + (b * Nq + n) * Mt + m];
    const float G2v  = g_s[OFF_G2 + (b * Nq + n) * Mt + m];
    const float smt  = g_s[OFF_SMT + b * Mt + m];

    const float cmask = (snsp - G1v) * (1.0f / (float)HWP);
    const float cdice = 1.f - __fdividef(2.f * G2v + 1.f, snpm + smt + 1.f);

    int sid = sids[b * Mt + m];
    sid = sid < 0 ? 0 : (sid > 3 ? 3 : sid);
    float pr = (sid == 0) ? e0 : (sid == 1) ? e1 : (sid == 2) ? e2 : e3;
    pr *= inv;

    float c = -2.f * p1 + 5.f * cmask + 5.f * cdice - pr;
    if (!isfinite(c)) c = isnan(c) ? 10000.f : (c > 0.f ? 10000.f : -10000.f);
    out[(b * Nq + n) * Mt + m] = c;
}

extern "C" void kernel_launch(void* const* d_in, const int* in_sizes, int n_in,
                              void* d_out, int out_size)
{
    const float* pred_logits = (const float*)d_in[0];  // [4,100,2]
    const float* pred_masks  = (const float*)d_in[1];  // [4,100,256,256]
    const float* pred_style  = (const float*)d_in[2];  // [4,100,4]
    const float* tgt_masks   = (const float*)d_in[3];  // [4,50,256,256]
    const int*   styles      = (const int*)d_in[4];    // [4,50]
    float* out = (float*)d_out;                        // [4,100,50]

    cudaFuncSetAttribute(cost_main, cudaFuncAttributeMaxDynamicSharedMemorySize, SMEM_BYTES);

    void* scratch = nullptr;
    cudaGetSymbolAddress(&scratch, g_s);
    cudaMemsetAsync(scratch, 0, SCRATCH_N * sizeof(float), 0);

    dim3 gmain(CTAS_PER_B, Bsz);
    cost_main<<<gmain, THREADS, SMEM_BYTES>>>(pred_masks, tgt_masks);
    dim3 gepi(Nq, Bsz);
    cost_epi<<<gepi, 64>>>(pred_logits, pred_style, styles, out);
}